// round 15
// baseline (speedup 1.0000x reference)
#include <cuda_runtime.h>
#include <cuda_fp16.h>
#include <cstdint>

#define N0 100000
#define N1 20000
#define N2 4000
#define E1 500000
#define E2 100000
#define FH 512
#define C_OUT 10

// ---------------- scratch ---------------------------------------------------
__device__ __half g_Xh [(size_t)N0 * FH];    // fp16 of x (all rows)
__device__ __half g_A1h[(size_t)N1 * FH];    // agg1 (fp16)
__device__ __half g_Hh [(size_t)N1 * FH];    // h (fp16)
__device__ __half g_Wt[4][(size_t)FH * FH];  // 0 rel1, 2 root1 (transposed fp16)
__device__ float g_Wcomb[(size_t)FH * C_OUT];
__device__ float g_bcomb[C_OUT];
#define WC2_PITCH 21
#define WC2_MAT (256 * WC2_PITCH)
__device__ float g_Wc2[2 * WC2_MAT];
__device__ float g_bc2[C_OUT];
__device__ int   g_gcur;   // gather work-queue cursor (reset in launch C)

// CSR scratch. cnt arrays zero at module load; re-zeroed at end of launch C.
__device__ int g_cnt1[N1], g_rp1[N1 + 1], g_pos1[N1], g_esrc1[E1];
__device__ int g_cnt2[N2], g_rp2[N2 + 1], g_pos2[N2], g_esrc2[E2];

// ---------------- helpers ---------------------------------------------------
__device__ __forceinline__ uint32_t smem_u32(const void* p) {
    uint32_t a;
    asm("{ .reg .u64 t; cvta.to.shared.u64 t, %1; cvt.u32.u64 %0, t; }"
        : "=r"(a) : "l"(p));
    return a;
}
__device__ __forceinline__ void cp_async16(uint32_t dst, const void* src, int sz) {
    asm volatile("cp.async.cg.shared.global [%0], [%1], 16, %2;"
                 :: "r"(dst), "l"(src), "r"(sz) : "memory");
}
__device__ __forceinline__ void cp_commit() {
    asm volatile("cp.async.commit_group;" ::: "memory");
}
__device__ __forceinline__ void cp_wait1() {
    asm volatile("cp.async.wait_group 1;" ::: "memory");
}
__device__ __forceinline__ uint32_t pack2(__half a, __half b) {
    __half2 t = __halves2half2(a, b);
    return *reinterpret_cast<uint32_t*>(&t);
}
__device__ __forceinline__ float2 h2f(uint32_t w) {
    __half2 t = *reinterpret_cast<__half2*>(&w);
    return __half22float2(t);
}
__device__ __forceinline__ __half2 u2h2(uint32_t w) {
    return *reinterpret_cast<__half2*>(&w);
}
__device__ __forceinline__ void mma16816(float* c, const uint32_t* a,
                                         uint32_t b0, uint32_t b1) {
    asm("mma.sync.aligned.m16n8k16.row.col.f32.f16.f16.f32 "
        "{%0,%1,%2,%3}, {%4,%5,%6,%7}, {%8,%9}, {%0,%1,%2,%3};"
        : "+f"(c[0]), "+f"(c[1]), "+f"(c[2]), "+f"(c[3])
        : "r"(a[0]), "r"(a[1]), "r"(a[2]), "r"(a[3]), "r"(b0), "r"(b1));
}
#define LDX4(r, addr) \
    asm volatile("ldmatrix.sync.aligned.m8n8.x4.shared.b16 {%0,%1,%2,%3}, [%4];" \
                 : "=r"((r)[0]), "=r"((r)[1]), "=r"((r)[2]), "=r"((r)[3])        \
                 : "r"(addr))

// ---------------- x -> fp16 chunk converter ----------------------------------
#define NCH_TOTAL ((N0 * FH) / 8)
__device__ __forceinline__ void conv_chunk(const float4* __restrict__ x4,
                                           uint4* __restrict__ Xh4, int i) {
    float4 v0 = x4[2 * i], v1 = x4[2 * i + 1];
    Xh4[i] = make_uint4(
        pack2(__float2half_rn(v0.x), __float2half_rn(v0.y)),
        pack2(__float2half_rn(v0.z), __float2half_rn(v0.w)),
        pack2(__float2half_rn(v1.x), __float2half_rn(v1.y)),
        pack2(__float2half_rn(v1.z), __float2half_rn(v1.w)));
}

// ---------------- folded prep bodies ------------------------------------------
__device__ __forceinline__ void transpose_body(
    const float* __restrict__ W, __half* __restrict__ Bh,
    int bx, int by, int tx, int ty, float (*t)[33]) {
    int n0 = bx * 32, k0 = by * 32;
    for (int yy = ty; yy < 32; yy += 8)
        t[yy][tx] = W[(size_t)(k0 + yy) * FH + n0 + tx];
    __syncthreads();
    for (int yy = ty; yy < 32; yy += 8)
        Bh[(size_t)(n0 + yy) * FH + k0 + tx] = __float2half_rn(t[tx][yy]);
}

__device__ __forceinline__ void wcomb_body(
    int k, int lane,
    const float* __restrict__ Wlin, const float* __restrict__ Whead,
    const float* __restrict__ blin, const float* __restrict__ bhead,
    float* __restrict__ Wcomb, float* __restrict__ bcomb) {
    const float* rowv = (k < FH) ? (Wlin + (size_t)k * FH) : blin;
    float acc[C_OUT];
#pragma unroll
    for (int c = 0; c < C_OUT; ++c) acc[c] = 0.f;
    for (int j = lane; j < FH; j += 32) {
        float v = rowv[j];
        const float* w = Whead + (size_t)j * C_OUT;
#pragma unroll
        for (int c = 0; c < C_OUT; ++c) acc[c] += v * w[c];
    }
#pragma unroll
    for (int off = 16; off > 0; off >>= 1)
#pragma unroll
        for (int c = 0; c < C_OUT; ++c)
            acc[c] += __shfl_down_sync(0xFFFFFFFFu, acc[c], off);
    if (lane == 0) {
        if (k < FH) {
#pragma unroll
            for (int c = 0; c < C_OUT; ++c) Wcomb[(size_t)k * C_OUT + c] = acc[c];
        } else {
#pragma unroll
            for (int c = 0; c < C_OUT; ++c) bcomb[c] = acc[c] + bhead[c];
        }
    }
}

__device__ __forceinline__ void wfold_body(
    int idx, int lane,
    const float* __restrict__ Wrel2, const float* __restrict__ Wroot2,
    const float* __restrict__ brel2,
    const float* __restrict__ Wcomb, const float* __restrict__ bcomb,
    float* __restrict__ Wc2, float* __restrict__ bc2) {
    float acc[C_OUT];
#pragma unroll
    for (int c = 0; c < C_OUT; ++c) acc[c] = 0.f;
    if (idx < 2 * FH) {
        int m = idx >> 9, k = idx & (FH - 1);
        const float* W = m ? Wroot2 : Wrel2;
        for (int j = lane; j < FH; j += 32) {
            float v = W[(size_t)k * FH + j];
            const float* wc = Wcomb + (size_t)j * C_OUT;
#pragma unroll
            for (int c = 0; c < C_OUT; ++c) acc[c] += v * wc[c];
        }
#pragma unroll
        for (int off = 16; off > 0; off >>= 1)
#pragma unroll
            for (int c = 0; c < C_OUT; ++c)
                acc[c] += __shfl_down_sync(0xFFFFFFFFu, acc[c], off);
        if (lane == 0) {
            int p = k >> 1, dd = k & 1;
            float* dst = Wc2 + (size_t)m * WC2_MAT + p * WC2_PITCH + dd * C_OUT;
#pragma unroll
            for (int c = 0; c < C_OUT; ++c) dst[c] = acc[c];
        }
    } else if (idx == 2 * FH) {
        for (int j = lane; j < FH; j += 32) {
            float v = brel2[j];
            const float* wc = Wcomb + (size_t)j * C_OUT;
#pragma unroll
            for (int c = 0; c < C_OUT; ++c) acc[c] += v * wc[c];
        }
#pragma unroll
        for (int off = 16; off > 0; off >>= 1)
#pragma unroll
            for (int c = 0; c < C_OUT; ++c)
                acc[c] += __shfl_down_sync(0xFFFFFFFFu, acc[c], off);
        if (lane == 0) {
#pragma unroll
            for (int c = 0; c < C_OUT; ++c) bc2[c] = acc[c] + bcomb[c];
        }
    }
}

// ---------------- launch A: hist + ALL conv + transposes + wcomb --------------
__global__ void hist_all(const int* __restrict__ d1, const int* __restrict__ d2,
                         int* __restrict__ c1, int* __restrict__ c2,
                         int hb, int cb, int tb,
                         const float4* __restrict__ x4, uint4* __restrict__ Xh4,
                         const float* __restrict__ W0, const float* __restrict__ W1,
                         __half* __restrict__ Wt,
                         const float* __restrict__ Wlin, const float* __restrict__ Whead,
                         const float* __restrict__ blin, const float* __restrict__ bhead,
                         float* __restrict__ Wcomb, float* __restrict__ bcomb) {
    int bid = blockIdx.x;
    if (bid < hb) {
        int e = bid * blockDim.x + threadIdx.x;
        if (e < E1) atomicAdd(&c1[d1[e]], 1);
        else if (e < E1 + E2) atomicAdd(&c2[d2[e - E1]], 1);
    } else if (bid < hb + cb) {
        int i = (bid - hb) * blockDim.x + threadIdx.x;
        if (i < NCH_TOTAL) conv_chunk(x4, Xh4, i);
    } else if (bid < hb + cb + tb) {
        __shared__ float t[32][33];
        int idx = bid - hb - cb;
        int z = idx >> 8;
        int rem = idx & 255;
        const float* W = z ? W1 : W0;
        __half* Bh = Wt + (size_t)(2 * z) * FH * FH;
        transpose_body(W, Bh, rem & 15, rem >> 4,
                       threadIdx.x & 31, threadIdx.x >> 5, t);
    } else {
        int k = (bid - hb - cb - tb) * 8 + (threadIdx.x >> 5);
        if (k <= FH)
            wcomb_body(k, threadIdx.x & 31, Wlin, Whead, blin, bhead, Wcomb, bcomb);
    }
}

// ---------------- launch B: scan ----------------------------------------------
__global__ __launch_bounds__(1024) void scan_both(
    const int* __restrict__ c1, int* __restrict__ r1, int* __restrict__ p1,
    const int* __restrict__ c2, int* __restrict__ r2, int* __restrict__ p2) {
    const int n = blockIdx.x ? N2 : N1;
    const int* cnt = blockIdx.x ? c2 : c1;
    int* rowptr = blockIdx.x ? r2 : r1;
    int* pos    = blockIdx.x ? p2 : p1;
    __shared__ int ts[1024];
    const int t = threadIdx.x;
    const int C = (n + 1023) >> 10;
    int local[20];
    int s = 0;
    for (int j = 0; j < C; ++j) {
        int idx = t * C + j;
        int v = (idx < n) ? cnt[idx] : 0;
        local[j] = s; s += v;
    }
    ts[t] = s;
    __syncthreads();
    for (int off = 1; off < 1024; off <<= 1) {
        int v = (t >= off) ? ts[t - off] : 0;
        __syncthreads();
        ts[t] += v;
        __syncthreads();
    }
    int base = (t > 0) ? ts[t - 1] : 0;
    for (int j = 0; j < C; ++j) {
        int idx = t * C + j;
        if (idx < n) { int r = base + local[j]; rowptr[idx] = r; pos[idx] = r; }
    }
    if (t == 1023) rowptr[n] = ts[1023];
}

// ---------------- launch C: fill + wfold + cnt re-zero + gcur reset -----------
__global__ void fill_wf_zero(const int* __restrict__ d1, const int* __restrict__ s1,
                             int* __restrict__ p1, int* __restrict__ e1,
                             const int* __restrict__ d2, const int* __restrict__ s2,
                             int* __restrict__ p2, int* __restrict__ e2,
                             int fb, int wb,
                             const float* __restrict__ Wrel2, const float* __restrict__ Wroot2,
                             const float* __restrict__ brel2,
                             const float* __restrict__ Wcomb, const float* __restrict__ bcomb,
                             float* __restrict__ Wc2, float* __restrict__ bc2,
                             int* __restrict__ c1, int* __restrict__ c2) {
    int bid = blockIdx.x;
    if (bid == 0 && threadIdx.x == 0) g_gcur = 0;
    if (bid < fb) {
        int e = bid * blockDim.x + threadIdx.x;
        if (e < E1) {
            int p = atomicAdd(&p1[d1[e]], 1);
            e1[p] = s1[e];
        } else if (e < E1 + E2) {
            int q = e - E1;
            int p = atomicAdd(&p2[d2[q]], 1);
            e2[p] = s2[q];
        }
    } else if (bid < fb + wb) {
        int idx = (bid - fb) * 8 + (threadIdx.x >> 5);
        wfold_body(idx, threadIdx.x & 31, Wrel2, Wroot2, brel2, Wcomb, bcomb,
                   Wc2, bc2);
    } else {
        int i = (bid - fb - wb) * blockDim.x + threadIdx.x;
        if (i < N1) c1[i] = 0;
        else if (i < N1 + N2) c2[i - N1] = 0;
    }
}

// ---------------- gather: persistent grid + global queue, fp16 batch adds -----
// Subrow u = row*2 + half; warp grabs batches of 4 subrows from g_gcur.
__global__ void gather_hi(const __half* __restrict__ Xh,
                          const int* __restrict__ esrc,
                          const int* __restrict__ rowptr, int nrows,
                          __half* __restrict__ Ah) {
    const int lane = threadIdx.x & 31;
    const int nsub = nrows * 2;
    for (;;) {
        int s0 = 0;
        if (lane == 0) s0 = atomicAdd(&g_gcur, 4);
        s0 = __shfl_sync(0xFFFFFFFFu, s0, 0);
        if (s0 >= nsub) break;
        int lim = min(s0 + 4, nsub);
        for (int sub = s0; sub < lim; ++sub) {
            const int row = sub >> 1;
            const int colb = (sub & 1) * 256 + lane * 8;
            const int beg = rowptr[row], end = rowptr[row + 1];
            float acc[8];
#pragma unroll
            for (int j = 0; j < 8; ++j) acc[j] = 0.f;
            int i = beg;
            for (; i + 4 <= end; i += 4) {
                uint4 U0 = *(const uint4*)(Xh + (size_t)__ldg(&esrc[i])     * FH + colb);
                uint4 U1 = *(const uint4*)(Xh + (size_t)__ldg(&esrc[i + 1]) * FH + colb);
                uint4 U2 = *(const uint4*)(Xh + (size_t)__ldg(&esrc[i + 2]) * FH + colb);
                uint4 U3 = *(const uint4*)(Xh + (size_t)__ldg(&esrc[i + 3]) * FH + colb);
                uint32_t w0[4] = {U0.x, U0.y, U0.z, U0.w};
                uint32_t w1[4] = {U1.x, U1.y, U1.z, U1.w};
                uint32_t w2[4] = {U2.x, U2.y, U2.z, U2.w};
                uint32_t w3[4] = {U3.x, U3.y, U3.z, U3.w};
#pragma unroll
                for (int j = 0; j < 4; ++j) {
                    // fp16 pairwise batch-sum of 4 edges, then fp32 accumulate
                    __half2 s = __hadd2(__hadd2(u2h2(w0[j]), u2h2(w1[j])),
                                        __hadd2(u2h2(w2[j]), u2h2(w3[j])));
                    float2 f = __half22float2(s);
                    acc[2 * j]     += f.x;
                    acc[2 * j + 1] += f.y;
                }
            }
            for (; i < end; ++i) {
                uint4 U0 = *(const uint4*)(Xh + (size_t)__ldg(&esrc[i]) * FH + colb);
                uint32_t w0[4] = {U0.x, U0.y, U0.z, U0.w};
#pragma unroll
                for (int j = 0; j < 4; ++j) {
                    float2 a = h2f(w0[j]);
                    acc[2 * j]     += a.x;
                    acc[2 * j + 1] += a.y;
                }
            }
            uint4 o4;
            o4.x = pack2(__float2half_rn(acc[0]), __float2half_rn(acc[1]));
            o4.y = pack2(__float2half_rn(acc[2]), __float2half_rn(acc[3]));
            o4.z = pack2(__float2half_rn(acc[4]), __float2half_rn(acc[5]));
            o4.w = pack2(__float2half_rn(acc[6]), __float2half_rn(acc[7]));
            *(uint4*)(Ah + (size_t)row * FH + colb) = o4;
        }
    }
}

// ---------------- layer-1 GEMM (hi-only, 3-stage pipeline) -------------------
#define SA 40
#define NBUF 3

__global__ __launch_bounds__(256) void gemm1_hi(
    const __half* __restrict__ A0, const __half* __restrict__ B0,
    const __half* __restrict__ A1, const __half* __restrict__ B1,
    const float* __restrict__ bias,
    __half* __restrict__ Ch, int M) {
    extern __shared__ __half sm[];
    const int tid = threadIdx.x;
    const int lane = tid & 31;
    const int wid = tid >> 5;
    const int wm = wid & 3;
    const int wn = wid >> 2;
    const int m0 = blockIdx.y * 128;
    const int n0 = blockIdx.x * 128;

    float acc[2][8][4];
#pragma unroll
    for (int i = 0; i < 2; ++i)
#pragma unroll
        for (int j = 0; j < 8; ++j)
#pragma unroll
            for (int q = 0; q < 4; ++q) acc[i][j][q] = 0.f;

    const int r0 = tid >> 2;
    const int c8 = (tid & 3) * 8;

    auto tile_off = [&](int buf, int t, int row, int col) -> uint32_t {
        return (uint32_t)((((buf * 2 + t) * 128 + row) * SA + col) * 2);
    };
    const uint32_t smb = smem_u32(sm);

    constexpr int NST = 32;
    auto issue = [&](int buf, int s) {
        const int src = s >> 4;
        const int k0 = (s & 15) * 32;
        const __half* A = src ? A1 : A0;
        const __half* B = src ? B1 : B0;
#pragma unroll
        for (int i = 0; i < 2; ++i) {
            int row = r0 + i * 64;
            int gm = m0 + row;
            cp_async16(smb + tile_off(buf, 0, row, c8),
                       A + (size_t)gm * FH + k0 + c8, gm < M ? 16 : 0);
            cp_async16(smb + tile_off(buf, 1, row, c8),
                       B + (size_t)(n0 + row) * FH + k0 + c8, 16);
        }
        cp_commit();
    };

    issue(0, 0);
    issue(1, 1);

    const int lrow = lane & 15;
    const int lcol = (lane >> 4) << 3;
    const int fr = lane >> 2;
    const int fc = (lane & 3) * 2;

#pragma unroll 1
    for (int s = 0; s < NST; ++s) {
        cp_wait1();
        __syncthreads();
        if (s + 2 < NST) issue((s + 2) % NBUF, s + 2);
        else cp_commit();
        const int buf = s % NBUF;
#pragma unroll
        for (int kk = 0; kk < 32; kk += 16) {
            uint32_t ah[2][4], bb[4][4];
#pragma unroll
            for (int mi = 0; mi < 2; ++mi) {
                int rb = wm * 32 + mi * 16 + lrow;
                LDX4(ah[mi], smb + tile_off(buf, 0, rb, kk + lcol));
            }
#pragma unroll
            for (int np = 0; np < 4; ++np) {
                int nb = wn * 64 + np * 16 + lrow;
                LDX4(bb[np], smb + tile_off(buf, 1, nb, kk + lcol));
            }
#pragma unroll
            for (int np = 0; np < 4; ++np) {
#pragma unroll
                for (int mi = 0; mi < 2; ++mi) {
                    mma16816(acc[mi][2 * np],     ah[mi], bb[np][0], bb[np][2]);
                    mma16816(acc[mi][2 * np + 1], ah[mi], bb[np][1], bb[np][3]);
                }
            }
        }
    }

    // epilogue: relu + fp16
#pragma unroll
    for (int mi = 0; mi < 2; ++mi) {
#pragma unroll
        for (int half = 0; half < 2; ++half) {
            int row = m0 + wm * 32 + mi * 16 + fr + half * 8;
            if (row >= M) continue;
#pragma unroll
            for (int ni = 0; ni < 8; ++ni) {
                int col = n0 + wn * 64 + ni * 8 + fc;
                float v0 = fmaxf(acc[mi][ni][half * 2 + 0] + bias[col], 0.f);
                float v1 = fmaxf(acc[mi][ni][half * 2 + 1] + bias[col + 1], 0.f);
                *(uint32_t*)(Ch + (size_t)row * FH + col) =
                    pack2(__float2half_rn(v0), __float2half_rn(v1));
            }
        }
    }
}

// ---------------- fused layer 2 + head ---------------------------------------
__global__ __launch_bounds__(256) void layer2_fused(
    const uint32_t* __restrict__ Hh32,
    const int* __restrict__ esrc, const int* __restrict__ rowptr,
    const float* __restrict__ Wc2, const float* __restrict__ bc2,
    float* __restrict__ out) {
    __shared__ float ws[2 * WC2_MAT];
    __shared__ float bs[C_OUT];
    for (int i = threadIdx.x; i < 2 * WC2_MAT; i += 256) ws[i] = Wc2[i];
    if (threadIdx.x < C_OUT) bs[threadIdx.x] = bc2[threadIdx.x];
    __syncthreads();

    const int lane = threadIdx.x & 31;
    int row = blockIdx.x * 8 + (threadIdx.x >> 5);
    if (row >= N2) return;
    const int beg = rowptr[row], end = rowptr[row + 1];

    float agg[16];
#pragma unroll
    for (int j = 0; j < 16; ++j) agg[j] = 0.f;
    for (int i = beg; i < end; ++i) {
        const uint32_t* hrow = Hh32 + (size_t)__ldg(&esrc[i]) * 256;
#pragma unroll
        for (int q = 0; q < 8; ++q) {
            float2 f = h2f(hrow[lane + 32 * q]);
            agg[2 * q]     += f.x;
            agg[2 * q + 1] += f.y;
        }
    }
    float hr[16];
    {
        const uint32_t* rrow = Hh32 + (size_t)row * 256;
#pragma unroll
        for (int q = 0; q < 8; ++q) {
            float2 f = h2f(rrow[lane + 32 * q]);
            hr[2 * q]     = f.x;
            hr[2 * q + 1] = f.y;
        }
    }
    float res[C_OUT];
#pragma unroll
    for (int c = 0; c < C_OUT; ++c) res[c] = 0.f;
    const float* wrel  = ws;
    const float* wroot = ws + WC2_MAT;
#pragma unroll
    for (int q = 0; q < 8; ++q) {
        int p = lane + 32 * q;
        const float* w0 = wrel  + p * WC2_PITCH;
        const float* w1 = wroot + p * WC2_PITCH;
#pragma unroll
        for (int c = 0; c < C_OUT; ++c) {
            res[c] += agg[2 * q]     * w0[c]
                    + agg[2 * q + 1] * w0[C_OUT + c]
                    + hr[2 * q]      * w1[c]
                    + hr[2 * q + 1]  * w1[C_OUT + c];
        }
    }
#pragma unroll
    for (int off = 16; off > 0; off >>= 1)
#pragma unroll
        for (int c = 0; c < C_OUT; ++c)
            res[c] += __shfl_down_sync(0xFFFFFFFFu, res[c], off);
    if (lane == 0) {
#pragma unroll
        for (int c = 0; c < C_OUT; ++c)
            out[(size_t)row * C_OUT + c] = res[c] + bs[c];
    }
}

// ---------------------------------------------------------------------------
extern "C" void kernel_launch(void* const* d_in, const int* in_sizes, int n_in,
                              void* d_out, int out_size) {
    const float* x     = (const float*)d_in[0];
    const int*   src1  = (const int*)  d_in[1];
    const int*   dst1  = (const int*)  d_in[2];
    const int*   src2  = (const int*)  d_in[3];
    const int*   dst2  = (const int*)  d_in[4];
    const float* Wrel1 = (const float*)d_in[5];
    const float* brel1 = (const float*)d_in[6];
    const float* Wroot1= (const float*)d_in[7];
    const float* Wrel2 = (const float*)d_in[8];
    const float* brel2 = (const float*)d_in[9];
    const float* Wroot2= (const float*)d_in[10];
    const float* Wlin  = (const float*)d_in[11];
    const float* blin  = (const float*)d_in[12];
    const float* Whead = (const float*)d_in[13];
    const float* bhead = (const float*)d_in[14];
    float* out = (float*)d_out;

    float *Wcomb, *bcomb, *Wc2, *bc2;
    __half *Xh, *A1h, *Hh, *Wt;
    int *cnt1, *rp1, *pos1, *esrc1, *cnt2, *rp2, *pos2, *esrc2;
    cudaGetSymbolAddress((void**)&Xh,   g_Xh);
    cudaGetSymbolAddress((void**)&A1h,  g_A1h);
    cudaGetSymbolAddress((void**)&Hh,   g_Hh);
    cudaGetSymbolAddress((void**)&Wt,   g_Wt);
    cudaGetSymbolAddress((void**)&Wcomb, g_Wcomb);
    cudaGetSymbolAddress((void**)&bcomb, g_bcomb);
    cudaGetSymbolAddress((void**)&Wc2,  g_Wc2);
    cudaGetSymbolAddress((void**)&bc2,  g_bc2);
    cudaGetSymbolAddress((void**)&cnt1, g_cnt1);
    cudaGetSymbolAddress((void**)&rp1,  g_rp1);
    cudaGetSymbolAddress((void**)&pos1, g_pos1);
    cudaGetSymbolAddress((void**)&esrc1, g_esrc1);
    cudaGetSymbolAddress((void**)&cnt2, g_cnt2);
    cudaGetSymbolAddress((void**)&rp2,  g_rp2);
    cudaGetSymbolAddress((void**)&pos2, g_pos2);
    cudaGetSymbolAddress((void**)&esrc2, g_esrc2);
    __half* Wrel1T = Wt;
    __half* Wroot1T = Wt + (size_t)2 * FH * FH;

    constexpr int GSMEM = NBUF * 2 * 128 * SA * 2;  // 61440 B
    cudaFuncSetAttribute(gemm1_hi,
                         cudaFuncAttributeMaxDynamicSharedMemorySize, GSMEM);

    // ---- launch A: hist + ALL conv + transposes + wcomb ----
    {
        int hb = (E1 + E2 + 255) / 256;          // 2344
        int cb = (NCH_TOTAL + 255) / 256;        // 25000
        int tb = 512;
        int wb = (FH + 1 + 7) / 8;               // 65
        hist_all<<<hb + cb + tb + wb, 256>>>(
            dst1, dst2, cnt1, cnt2, hb, cb, tb,
            (const float4*)x, (uint4*)Xh,
            Wrel1, Wroot1, Wt,
            Wlin, Whead, blin, bhead, Wcomb, bcomb);
    }
    // ---- launch B: scan ----
    scan_both<<<2, 1024>>>(cnt1, rp1, pos1, cnt2, rp2, pos2);
    // ---- launch C: fill + wfold + cnt re-zero + gcur reset ----
    {
        int fb = (E1 + E2 + 255) / 256;          // 2344
        int wb = (2 * FH + 1 + 7) / 8;           // 129
        int zb = (N1 + N2 + 255) / 256;          // 94
        fill_wf_zero<<<fb + wb + zb, 256>>>(
            dst1, src1, pos1, esrc1, dst2, src2, pos2, esrc2, fb, wb,
            Wrel2, Wroot2, brel2, Wcomb, bcomb, Wc2, bc2, cnt1, cnt2);
    }

    // ---- layer 1 ----
    gather_hi<<<888, 256>>>(Xh, esrc1, rp1, N1, A1h);   // 148 SMs x 6 CTAs
    {
        dim3 grid(FH / 128, (N1 + 127) / 128);
        gemm1_hi<<<grid, 256, GSMEM>>>(
            A1h, Wrel1T, Xh, Wroot1T, brel1, Hh, N1);
    }

    // ---- fused layer 2 + head ----
    layer2_fused<<<(N2 + 7) / 8, 256>>>(
        (const uint32_t*)Hh, esrc2, rp2, Wc2, bc2, out);

    (void)in_sizes; (void)n_in; (void)out_size;
}

// round 16
// speedup vs baseline: 1.0306x; 1.0306x over previous
#include <cuda_runtime.h>
#include <cuda_fp16.h>
#include <cstdint>

#define N0 100000
#define N1 20000
#define N2 4000
#define E1 500000
#define E2 100000
#define FH 512
#define C_OUT 10

// ---------------- scratch ---------------------------------------------------
__device__ __half g_Xh [(size_t)N0 * FH];    // fp16 of x (all rows)
__device__ __half g_A1h[(size_t)N1 * FH];    // agg1 (fp16)
__device__ __half g_Hh [(size_t)N1 * FH];    // h (fp16)
__device__ __half g_Wt[4][(size_t)FH * FH];  // 0 rel1, 2 root1 (transposed fp16)
__device__ float g_Wcomb[(size_t)FH * C_OUT];
__device__ float g_bcomb[C_OUT];
#define WC2_PITCH 21
#define WC2_MAT (256 * WC2_PITCH)
__device__ float g_Wc2[2 * WC2_MAT];
__device__ float g_bc2[C_OUT];

// CSR scratch. cnt arrays zero at module load; re-zeroed at end of launch C.
__device__ int g_cnt1[N1], g_rp1[N1 + 1], g_pos1[N1], g_esrc1[E1];
__device__ int g_cnt2[N2], g_rp2[N2 + 1], g_pos2[N2], g_esrc2[E2];

// ---------------- helpers ---------------------------------------------------
__device__ __forceinline__ uint32_t smem_u32(const void* p) {
    uint32_t a;
    asm("{ .reg .u64 t; cvta.to.shared.u64 t, %1; cvt.u32.u64 %0, t; }"
        : "=r"(a) : "l"(p));
    return a;
}
__device__ __forceinline__ void cp_async16(uint32_t dst, const void* src, int sz) {
    asm volatile("cp.async.cg.shared.global [%0], [%1], 16, %2;"
                 :: "r"(dst), "l"(src), "r"(sz) : "memory");
}
__device__ __forceinline__ void cp_commit() {
    asm volatile("cp.async.commit_group;" ::: "memory");
}
__device__ __forceinline__ void cp_wait1() {
    asm volatile("cp.async.wait_group 1;" ::: "memory");
}
__device__ __forceinline__ uint32_t pack2(__half a, __half b) {
    __half2 t = __halves2half2(a, b);
    return *reinterpret_cast<uint32_t*>(&t);
}
__device__ __forceinline__ float2 h2f(uint32_t w) {
    __half2 t = *reinterpret_cast<__half2*>(&w);
    return __half22float2(t);
}
__device__ __forceinline__ __half2 u2h2(uint32_t w) {
    return *reinterpret_cast<__half2*>(&w);
}
__device__ __forceinline__ void mma16816(float* c, const uint32_t* a,
                                         uint32_t b0, uint32_t b1) {
    asm("mma.sync.aligned.m16n8k16.row.col.f32.f16.f16.f32 "
        "{%0,%1,%2,%3}, {%4,%5,%6,%7}, {%8,%9}, {%0,%1,%2,%3};"
        : "+f"(c[0]), "+f"(c[1]), "+f"(c[2]), "+f"(c[3])
        : "r"(a[0]), "r"(a[1]), "r"(a[2]), "r"(a[3]), "r"(b0), "r"(b1));
}
#define LDX4(r, addr) \
    asm volatile("ldmatrix.sync.aligned.m8n8.x4.shared.b16 {%0,%1,%2,%3}, [%4];" \
                 : "=r"((r)[0]), "=r"((r)[1]), "=r"((r)[2]), "=r"((r)[3])        \
                 : "r"(addr))

// ---------------- x -> fp16 chunk converter ----------------------------------
#define NCH_TOTAL ((N0 * FH) / 8)
__device__ __forceinline__ void conv_chunk(const float4* __restrict__ x4,
                                           uint4* __restrict__ Xh4, int i) {
    float4 v0 = x4[2 * i], v1 = x4[2 * i + 1];
    Xh4[i] = make_uint4(
        pack2(__float2half_rn(v0.x), __float2half_rn(v0.y)),
        pack2(__float2half_rn(v0.z), __float2half_rn(v0.w)),
        pack2(__float2half_rn(v1.x), __float2half_rn(v1.y)),
        pack2(__float2half_rn(v1.z), __float2half_rn(v1.w)));
}

// ---------------- folded prep bodies ------------------------------------------
__device__ __forceinline__ void transpose_body(
    const float* __restrict__ W, __half* __restrict__ Bh,
    int bx, int by, int tx, int ty, float (*t)[33]) {
    int n0 = bx * 32, k0 = by * 32;
    for (int yy = ty; yy < 32; yy += 8)
        t[yy][tx] = W[(size_t)(k0 + yy) * FH + n0 + tx];
    __syncthreads();
    for (int yy = ty; yy < 32; yy += 8)
        Bh[(size_t)(n0 + yy) * FH + k0 + tx] = __float2half_rn(t[tx][yy]);
}

__device__ __forceinline__ void wcomb_body(
    int k, int lane,
    const float* __restrict__ Wlin, const float* __restrict__ Whead,
    const float* __restrict__ blin, const float* __restrict__ bhead,
    float* __restrict__ Wcomb, float* __restrict__ bcomb) {
    const float* rowv = (k < FH) ? (Wlin + (size_t)k * FH) : blin;
    float acc[C_OUT];
#pragma unroll
    for (int c = 0; c < C_OUT; ++c) acc[c] = 0.f;
    for (int j = lane; j < FH; j += 32) {
        float v = rowv[j];
        const float* w = Whead + (size_t)j * C_OUT;
#pragma unroll
        for (int c = 0; c < C_OUT; ++c) acc[c] += v * w[c];
    }
#pragma unroll
    for (int off = 16; off > 0; off >>= 1)
#pragma unroll
        for (int c = 0; c < C_OUT; ++c)
            acc[c] += __shfl_down_sync(0xFFFFFFFFu, acc[c], off);
    if (lane == 0) {
        if (k < FH) {
#pragma unroll
            for (int c = 0; c < C_OUT; ++c) Wcomb[(size_t)k * C_OUT + c] = acc[c];
        } else {
#pragma unroll
            for (int c = 0; c < C_OUT; ++c) bcomb[c] = acc[c] + bhead[c];
        }
    }
}

__device__ __forceinline__ void wfold_body(
    int idx, int lane,
    const float* __restrict__ Wrel2, const float* __restrict__ Wroot2,
    const float* __restrict__ brel2,
    const float* __restrict__ Wcomb, const float* __restrict__ bcomb,
    float* __restrict__ Wc2, float* __restrict__ bc2) {
    float acc[C_OUT];
#pragma unroll
    for (int c = 0; c < C_OUT; ++c) acc[c] = 0.f;
    if (idx < 2 * FH) {
        int m = idx >> 9, k = idx & (FH - 1);
        const float* W = m ? Wroot2 : Wrel2;
        for (int j = lane; j < FH; j += 32) {
            float v = W[(size_t)k * FH + j];
            const float* wc = Wcomb + (size_t)j * C_OUT;
#pragma unroll
            for (int c = 0; c < C_OUT; ++c) acc[c] += v * wc[c];
        }
#pragma unroll
        for (int off = 16; off > 0; off >>= 1)
#pragma unroll
            for (int c = 0; c < C_OUT; ++c)
                acc[c] += __shfl_down_sync(0xFFFFFFFFu, acc[c], off);
        if (lane == 0) {
            int p = k >> 1, dd = k & 1;
            float* dst = Wc2 + (size_t)m * WC2_MAT + p * WC2_PITCH + dd * C_OUT;
#pragma unroll
            for (int c = 0; c < C_OUT; ++c) dst[c] = acc[c];
        }
    } else if (idx == 2 * FH) {
        for (int j = lane; j < FH; j += 32) {
            float v = brel2[j];
            const float* wc = Wcomb + (size_t)j * C_OUT;
#pragma unroll
            for (int c = 0; c < C_OUT; ++c) acc[c] += v * wc[c];
        }
#pragma unroll
        for (int off = 16; off > 0; off >>= 1)
#pragma unroll
            for (int c = 0; c < C_OUT; ++c)
                acc[c] += __shfl_down_sync(0xFFFFFFFFu, acc[c], off);
        if (lane == 0) {
#pragma unroll
            for (int c = 0; c < C_OUT; ++c) bc2[c] = acc[c] + bcomb[c];
        }
    }
}

// ---------------- launch A: hist + ALL conv + transposes + wcomb --------------
__global__ void hist_all(const int* __restrict__ d1, const int* __restrict__ d2,
                         int* __restrict__ c1, int* __restrict__ c2,
                         int hb, int cb, int tb,
                         const float4* __restrict__ x4, uint4* __restrict__ Xh4,
                         const float* __restrict__ W0, const float* __restrict__ W1,
                         __half* __restrict__ Wt,
                         const float* __restrict__ Wlin, const float* __restrict__ Whead,
                         const float* __restrict__ blin, const float* __restrict__ bhead,
                         float* __restrict__ Wcomb, float* __restrict__ bcomb) {
    int bid = blockIdx.x;
    if (bid < hb) {
        int e = bid * blockDim.x + threadIdx.x;
        if (e < E1) atomicAdd(&c1[d1[e]], 1);
        else if (e < E1 + E2) atomicAdd(&c2[d2[e - E1]], 1);
    } else if (bid < hb + cb) {
        int i = (bid - hb) * blockDim.x + threadIdx.x;
        if (i < NCH_TOTAL) conv_chunk(x4, Xh4, i);
    } else if (bid < hb + cb + tb) {
        __shared__ float t[32][33];
        int idx = bid - hb - cb;
        int z = idx >> 8;
        int rem = idx & 255;
        const float* W = z ? W1 : W0;
        __half* Bh = Wt + (size_t)(2 * z) * FH * FH;
        transpose_body(W, Bh, rem & 15, rem >> 4,
                       threadIdx.x & 31, threadIdx.x >> 5, t);
    } else {
        int k = (bid - hb - cb - tb) * 8 + (threadIdx.x >> 5);
        if (k <= FH)
            wcomb_body(k, threadIdx.x & 31, Wlin, Whead, blin, bhead, Wcomb, bcomb);
    }
}

// ---------------- launch B: scan ----------------------------------------------
__global__ __launch_bounds__(1024) void scan_both(
    const int* __restrict__ c1, int* __restrict__ r1, int* __restrict__ p1,
    const int* __restrict__ c2, int* __restrict__ r2, int* __restrict__ p2) {
    const int n = blockIdx.x ? N2 : N1;
    const int* cnt = blockIdx.x ? c2 : c1;
    int* rowptr = blockIdx.x ? r2 : r1;
    int* pos    = blockIdx.x ? p2 : p1;
    __shared__ int ts[1024];
    const int t = threadIdx.x;
    const int C = (n + 1023) >> 10;
    int local[20];
    int s = 0;
    for (int j = 0; j < C; ++j) {
        int idx = t * C + j;
        int v = (idx < n) ? cnt[idx] : 0;
        local[j] = s; s += v;
    }
    ts[t] = s;
    __syncthreads();
    for (int off = 1; off < 1024; off <<= 1) {
        int v = (t >= off) ? ts[t - off] : 0;
        __syncthreads();
        ts[t] += v;
        __syncthreads();
    }
    int base = (t > 0) ? ts[t - 1] : 0;
    for (int j = 0; j < C; ++j) {
        int idx = t * C + j;
        if (idx < n) { int r = base + local[j]; rowptr[idx] = r; pos[idx] = r; }
    }
    if (t == 1023) rowptr[n] = ts[1023];
}

// ---------------- launch C: fill + wfold + cnt re-zero -------------------------
__global__ void fill_wf_zero(const int* __restrict__ d1, const int* __restrict__ s1,
                             int* __restrict__ p1, int* __restrict__ e1,
                             const int* __restrict__ d2, const int* __restrict__ s2,
                             int* __restrict__ p2, int* __restrict__ e2,
                             int fb, int wb,
                             const float* __restrict__ Wrel2, const float* __restrict__ Wroot2,
                             const float* __restrict__ brel2,
                             const float* __restrict__ Wcomb, const float* __restrict__ bcomb,
                             float* __restrict__ Wc2, float* __restrict__ bc2,
                             int* __restrict__ c1, int* __restrict__ c2) {
    int bid = blockIdx.x;
    if (bid < fb) {
        int e = bid * blockDim.x + threadIdx.x;
        if (e < E1) {
            int p = atomicAdd(&p1[d1[e]], 1);
            e1[p] = s1[e];
        } else if (e < E1 + E2) {
            int q = e - E1;
            int p = atomicAdd(&p2[d2[q]], 1);
            e2[p] = s2[q];
        }
    } else if (bid < fb + wb) {
        int idx = (bid - fb) * 8 + (threadIdx.x >> 5);
        wfold_body(idx, threadIdx.x & 31, Wrel2, Wroot2, brel2, Wcomb, bcomb,
                   Wc2, bc2);
    } else {
        int i = (bid - fb - wb) * blockDim.x + threadIdx.x;
        if (i < N1) c1[i] = 0;
        else if (i < N1 + N2) c2[i - N1] = 0;
    }
}

// ---------------- gather: warp per HALF-ROW, block-local cursor, hadd2 -------
#define GSUB 32
__global__ void gather_hi(const __half* __restrict__ Xh,
                          const int* __restrict__ esrc,
                          const int* __restrict__ rowptr, int nrows,
                          __half* __restrict__ Ah) {
    __shared__ int cur;
    if (threadIdx.x == 0) cur = 0;
    __syncthreads();
    const int base = blockIdx.x * GSUB;
    const int lane = threadIdx.x & 31;
    const int nsub = nrows * 2;
    for (;;) {
        int r = 0;
        if (lane == 0) r = atomicAdd(&cur, 1);
        r = __shfl_sync(0xFFFFFFFFu, r, 0);
        if (r >= GSUB) break;
        int sub = base + r;
        if (sub >= nsub) break;
        const int row = sub >> 1;
        const int colb = (sub & 1) * 256 + lane * 8;
        const int beg = rowptr[row], end = rowptr[row + 1];
        float acc[8];
#pragma unroll
        for (int j = 0; j < 8; ++j) acc[j] = 0.f;
        int i = beg;
        for (; i + 4 <= end; i += 4) {
            uint4 U0 = *(const uint4*)(Xh + (size_t)__ldg(&esrc[i])     * FH + colb);
            uint4 U1 = *(const uint4*)(Xh + (size_t)__ldg(&esrc[i + 1]) * FH + colb);
            uint4 U2 = *(const uint4*)(Xh + (size_t)__ldg(&esrc[i + 2]) * FH + colb);
            uint4 U3 = *(const uint4*)(Xh + (size_t)__ldg(&esrc[i + 3]) * FH + colb);
            uint32_t w0[4] = {U0.x, U0.y, U0.z, U0.w};
            uint32_t w1[4] = {U1.x, U1.y, U1.z, U1.w};
            uint32_t w2[4] = {U2.x, U2.y, U2.z, U2.w};
            uint32_t w3[4] = {U3.x, U3.y, U3.z, U3.w};
#pragma unroll
            for (int j = 0; j < 4; ++j) {
                // fp16 pairwise batch-sum of 4 edges, then fp32 accumulate
                __half2 s = __hadd2(__hadd2(u2h2(w0[j]), u2h2(w1[j])),
                                    __hadd2(u2h2(w2[j]), u2h2(w3[j])));
                float2 f = __half22float2(s);
                acc[2 * j]     += f.x;
                acc[2 * j + 1] += f.y;
            }
        }
        for (; i < end; ++i) {
            uint4 U0 = *(const uint4*)(Xh + (size_t)__ldg(&esrc[i]) * FH + colb);
            uint32_t w0[4] = {U0.x, U0.y, U0.z, U0.w};
#pragma unroll
            for (int j = 0; j < 4; ++j) {
                float2 a = h2f(w0[j]);
                acc[2 * j]     += a.x;
                acc[2 * j + 1] += a.y;
            }
        }
        uint4 o4;
        o4.x = pack2(__float2half_rn(acc[0]), __float2half_rn(acc[1]));
        o4.y = pack2(__float2half_rn(acc[2]), __float2half_rn(acc[3]));
        o4.z = pack2(__float2half_rn(acc[4]), __float2half_rn(acc[5]));
        o4.w = pack2(__float2half_rn(acc[6]), __float2half_rn(acc[7]));
        *(uint4*)(Ah + (size_t)row * FH + colb) = o4;
    }
}

// ---------------- layer-1 GEMM (hi-only, 3-stage pipeline) -------------------
#define SA 40
#define NBUF 3

__global__ __launch_bounds__(256) void gemm1_hi(
    const __half* __restrict__ A0, const __half* __restrict__ B0,
    const __half* __restrict__ A1, const __half* __restrict__ B1,
    const float* __restrict__ bias,
    __half* __restrict__ Ch, int M) {
    extern __shared__ __half sm[];
    const int tid = threadIdx.x;
    const int lane = tid & 31;
    const int wid = tid >> 5;
    const int wm = wid & 3;
    const int wn = wid >> 2;
    const int m0 = blockIdx.y * 128;
    const int n0 = blockIdx.x * 128;

    float acc[2][8][4];
#pragma unroll
    for (int i = 0; i < 2; ++i)
#pragma unroll
        for (int j = 0; j < 8; ++j)
#pragma unroll
            for (int q = 0; q < 4; ++q) acc[i][j][q] = 0.f;

    const int r0 = tid >> 2;
    const int c8 = (tid & 3) * 8;

    auto tile_off = [&](int buf, int t, int row, int col) -> uint32_t {
        return (uint32_t)((((buf * 2 + t) * 128 + row) * SA + col) * 2);
    };
    const uint32_t smb = smem_u32(sm);

    constexpr int NST = 32;
    auto issue = [&](int buf, int s) {
        const int src = s >> 4;
        const int k0 = (s & 15) * 32;
        const __half* A = src ? A1 : A0;
        const __half* B = src ? B1 : B0;
#pragma unroll
        for (int i = 0; i < 2; ++i) {
            int row = r0 + i * 64;
            int gm = m0 + row;
            cp_async16(smb + tile_off(buf, 0, row, c8),
                       A + (size_t)gm * FH + k0 + c8, gm < M ? 16 : 0);
            cp_async16(smb + tile_off(buf, 1, row, c8),
                       B + (size_t)(n0 + row) * FH + k0 + c8, 16);
        }
        cp_commit();
    };

    issue(0, 0);
    issue(1, 1);

    const int lrow = lane & 15;
    const int lcol = (lane >> 4) << 3;
    const int fr = lane >> 2;
    const int fc = (lane & 3) * 2;

#pragma unroll 1
    for (int s = 0; s < NST; ++s) {
        cp_wait1();
        __syncthreads();
        if (s + 2 < NST) issue((s + 2) % NBUF, s + 2);
        else cp_commit();
        const int buf = s % NBUF;
#pragma unroll
        for (int kk = 0; kk < 32; kk += 16) {
            uint32_t ah[2][4], bb[4][4];
#pragma unroll
            for (int mi = 0; mi < 2; ++mi) {
                int rb = wm * 32 + mi * 16 + lrow;
                LDX4(ah[mi], smb + tile_off(buf, 0, rb, kk + lcol));
            }
#pragma unroll
            for (int np = 0; np < 4; ++np) {
                int nb = wn * 64 + np * 16 + lrow;
                LDX4(bb[np], smb + tile_off(buf, 1, nb, kk + lcol));
            }
#pragma unroll
            for (int np = 0; np < 4; ++np) {
#pragma unroll
                for (int mi = 0; mi < 2; ++mi) {
                    mma16816(acc[mi][2 * np],     ah[mi], bb[np][0], bb[np][2]);
                    mma16816(acc[mi][2 * np + 1], ah[mi], bb[np][1], bb[np][3]);
                }
            }
        }
    }

    // epilogue: relu + fp16
#pragma unroll
    for (int mi = 0; mi < 2; ++mi) {
#pragma unroll
        for (int half = 0; half < 2; ++half) {
            int row = m0 + wm * 32 + mi * 16 + fr + half * 8;
            if (row >= M) continue;
#pragma unroll
            for (int ni = 0; ni < 8; ++ni) {
                int col = n0 + wn * 64 + ni * 8 + fc;
                float v0 = fmaxf(acc[mi][ni][half * 2 + 0] + bias[col], 0.f);
                float v1 = fmaxf(acc[mi][ni][half * 2 + 1] + bias[col + 1], 0.f);
                *(uint32_t*)(Ch + (size_t)row * FH + col) =
                    pack2(__float2half_rn(v0), __float2half_rn(v1));
            }
        }
    }
}

// ---------------- fused layer 2 + head ---------------------------------------
__global__ __launch_bounds__(256) void layer2_fused(
    const uint32_t* __restrict__ Hh32,
    const int* __restrict__ esrc, const int* __restrict__ rowptr,
    const float* __restrict__ Wc2, const float* __restrict__ bc2,
    float* __restrict__ out) {
    __shared__ float ws[2 * WC2_MAT];
    __shared__ float bs[C_OUT];
    for (int i = threadIdx.x; i < 2 * WC2_MAT; i += 256) ws[i] = Wc2[i];
    if (threadIdx.x < C_OUT) bs[threadIdx.x] = bc2[threadIdx.x];
    __syncthreads();

    const int lane = threadIdx.x & 31;
    int row = blockIdx.x * 8 + (threadIdx.x >> 5);
    if (row >= N2) return;
    const int beg = rowptr[row], end = rowptr[row + 1];

    float agg[16];
#pragma unroll
    for (int j = 0; j < 16; ++j) agg[j] = 0.f;
    for (int i = beg; i < end; ++i) {
        const uint32_t* hrow = Hh32 + (size_t)__ldg(&esrc[i]) * 256;
#pragma unroll
        for (int q = 0; q < 8; ++q) {
            float2 f = h2f(hrow[lane + 32 * q]);
            agg[2 * q]     += f.x;
            agg[2 * q + 1] += f.y;
        }
    }
    float hr[16];
    {
        const uint32_t* rrow = Hh32 + (size_t)row * 256;
#pragma unroll
        for (int q = 0; q < 8; ++q) {
            float2 f = h2f(rrow[lane + 32 * q]);
            hr[2 * q]     = f.x;
            hr[2 * q + 1] = f.y;
        }
    }
    float res[C_OUT];
#pragma unroll
    for (int c = 0; c < C_OUT; ++c) res[c] = 0.f;
    const float* wrel  = ws;
    const float* wroot = ws + WC2_MAT;
#pragma unroll
    for (int q = 0; q < 8; ++q) {
        int p = lane + 32 * q;
        const float* w0 = wrel  + p * WC2_PITCH;
        const float* w1 = wroot + p * WC2_PITCH;
#pragma unroll
        for (int c = 0; c < C_OUT; ++c) {
            res[c] += agg[2 * q]     * w0[c]
                    + agg[2 * q + 1] * w0[C_OUT + c]
                    + hr[2 * q]      * w1[c]
                    + hr[2 * q + 1]  * w1[C_OUT + c];
        }
    }
#pragma unroll
    for (int off = 16; off > 0; off >>= 1)
#pragma unroll
        for (int c = 0; c < C_OUT; ++c)
            res[c] += __shfl_down_sync(0xFFFFFFFFu, res[c], off);
    if (lane == 0) {
#pragma unroll
        for (int c = 0; c < C_OUT; ++c)
            out[(size_t)row * C_OUT + c] = res[c] + bs[c];
    }
}

// ---------------------------------------------------------------------------
extern "C" void kernel_launch(void* const* d_in, const int* in_sizes, int n_in,
                              void* d_out, int out_size) {
    const float* x     = (const float*)d_in[0];
    const int*   src1  = (const int*)  d_in[1];
    const int*   dst1  = (const int*)  d_in[2];
    const int*   src2  = (const int*)  d_in[3];
    const int*   dst2  = (const int*)  d_in[4];
    const float* Wrel1 = (const float*)d_in[5];
    const float* brel1 = (const float*)d_in[6];
    const float* Wroot1= (const float*)d_in[7];
    const float* Wrel2 = (const float*)d_in[8];
    const float* brel2 = (const float*)d_in[9];
    const float* Wroot2= (const float*)d_in[10];
    const float* Wlin  = (const float*)d_in[11];
    const float* blin  = (const float*)d_in[12];
    const float* Whead = (const float*)d_in[13];
    const float* bhead = (const float*)d_in[14];
    float* out = (float*)d_out;

    float *Wcomb, *bcomb, *Wc2, *bc2;
    __half *Xh, *A1h, *Hh, *Wt;
    int *cnt1, *rp1, *pos1, *esrc1, *cnt2, *rp2, *pos2, *esrc2;
    cudaGetSymbolAddress((void**)&Xh,   g_Xh);
    cudaGetSymbolAddress((void**)&A1h,  g_A1h);
    cudaGetSymbolAddress((void**)&Hh,   g_Hh);
    cudaGetSymbolAddress((void**)&Wt,   g_Wt);
    cudaGetSymbolAddress((void**)&Wcomb, g_Wcomb);
    cudaGetSymbolAddress((void**)&bcomb, g_bcomb);
    cudaGetSymbolAddress((void**)&Wc2,  g_Wc2);
    cudaGetSymbolAddress((void**)&bc2,  g_bc2);
    cudaGetSymbolAddress((void**)&cnt1, g_cnt1);
    cudaGetSymbolAddress((void**)&rp1,  g_rp1);
    cudaGetSymbolAddress((void**)&pos1, g_pos1);
    cudaGetSymbolAddress((void**)&esrc1, g_esrc1);
    cudaGetSymbolAddress((void**)&cnt2, g_cnt2);
    cudaGetSymbolAddress((void**)&rp2,  g_rp2);
    cudaGetSymbolAddress((void**)&pos2, g_pos2);
    cudaGetSymbolAddress((void**)&esrc2, g_esrc2);
    __half* Wrel1T = Wt;
    __half* Wroot1T = Wt + (size_t)2 * FH * FH;

    constexpr int GSMEM = NBUF * 2 * 128 * SA * 2;  // 61440 B
    cudaFuncSetAttribute(gemm1_hi,
                         cudaFuncAttributeMaxDynamicSharedMemorySize, GSMEM);

    // ---- launch A: hist + ALL conv + transposes + wcomb ----
    {
        int hb = (E1 + E2 + 255) / 256;          // 2344
        int cb = (NCH_TOTAL + 255) / 256;        // 25000
        int tb = 512;
        int wb = (FH + 1 + 7) / 8;               // 65
        hist_all<<<hb + cb + tb + wb, 256>>>(
            dst1, dst2, cnt1, cnt2, hb, cb, tb,
            (const float4*)x, (uint4*)Xh,
            Wrel1, Wroot1, Wt,
            Wlin, Whead, blin, bhead, Wcomb, bcomb);
    }
    // ---- launch B: scan ----
    scan_both<<<2, 1024>>>(cnt1, rp1, pos1, cnt2, rp2, pos2);
    // ---- launch C: fill + wfold + cnt re-zero ----
    {
        int fb = (E1 + E2 + 255) / 256;          // 2344
        int wb = (2 * FH + 1 + 7) / 8;           // 129
        int zb = (N1 + N2 + 255) / 256;          // 94
        fill_wf_zero<<<fb + wb + zb, 256>>>(
            dst1, src1, pos1, esrc1, dst2, src2, pos2, esrc2, fb, wb,
            Wrel2, Wroot2, brel2, Wcomb, bcomb, Wc2, bc2, cnt1, cnt2);
    }

    // ---- layer 1 ----
    {
        int nsub = N1 * 2;
        gather_hi<<<(nsub + GSUB - 1) / GSUB, 256>>>(Xh, esrc1, rp1, N1, A1h);
    }
    {
        dim3 grid(FH / 128, (N1 + 127) / 128);
        gemm1_hi<<<grid, 256, GSMEM>>>(
            A1h, Wrel1T, Xh, Wroot1T, brel1, Hh, N1);
    }

    // ---- fused layer 2 + head ----
    layer2_fused<<<(N2 + 7) / 8, 256>>>(
        (const uint32_t*)Hh, esrc2, rp2, Wc2, bc2, out);

    (void)in_sizes; (void)n_in; (void)out_size;
}

// round 17
// speedup vs baseline: 1.0862x; 1.0539x over previous
#include <cuda_runtime.h>
#include <cuda_fp16.h>
#include <cstdint>

#define N0 100000
#define N1 20000
#define N2 4000
#define E1 500000
#define E2 100000
#define FH 512
#define C_OUT 10

// ---------------- scratch ---------------------------------------------------
__device__ __half g_Xh [(size_t)N0 * FH];    // fp16 of x (all rows)
__device__ __half g_A1h[(size_t)N1 * FH];    // agg1 (fp16)
__device__ __half g_Hh [(size_t)N1 * FH];    // h (fp16)
__device__ __half g_Wt[4][(size_t)FH * FH];  // 0 rel1, 2 root1 (transposed fp16)
__device__ float g_Wcomb[(size_t)FH * C_OUT];
__device__ float g_bcomb[C_OUT];
#define WC2_PITCH 21
#define WC2_MAT (256 * WC2_PITCH)
__device__ float g_Wc2[2 * WC2_MAT];
__device__ float g_bc2[C_OUT];

// CSR scratch. cnt arrays zero at module load; re-zeroed at end of launch C.
__device__ int g_cnt1[N1], g_rp1[N1 + 1], g_pos1[N1], g_esrc1[E1];
__device__ int g_cnt2[N2], g_rp2[N2 + 1], g_pos2[N2], g_esrc2[E2];

// ---------------- helpers ---------------------------------------------------
__device__ __forceinline__ uint32_t smem_u32(const void* p) {
    uint32_t a;
    asm("{ .reg .u64 t; cvta.to.shared.u64 t, %1; cvt.u32.u64 %0, t; }"
        : "=r"(a) : "l"(p));
    return a;
}
__device__ __forceinline__ void cp_async16(uint32_t dst, const void* src, int sz) {
    asm volatile("cp.async.cg.shared.global [%0], [%1], 16, %2;"
                 :: "r"(dst), "l"(src), "r"(sz) : "memory");
}
__device__ __forceinline__ void cp_commit() {
    asm volatile("cp.async.commit_group;" ::: "memory");
}
__device__ __forceinline__ void cp_wait1() {
    asm volatile("cp.async.wait_group 1;" ::: "memory");
}
__device__ __forceinline__ uint32_t pack2(__half a, __half b) {
    __half2 t = __halves2half2(a, b);
    return *reinterpret_cast<uint32_t*>(&t);
}
__device__ __forceinline__ float2 h2f(uint32_t w) {
    __half2 t = *reinterpret_cast<__half2*>(&w);
    return __half22float2(t);
}
__device__ __forceinline__ void mma16816(float* c, const uint32_t* a,
                                         uint32_t b0, uint32_t b1) {
    asm("mma.sync.aligned.m16n8k16.row.col.f32.f16.f16.f32 "
        "{%0,%1,%2,%3}, {%4,%5,%6,%7}, {%8,%9}, {%0,%1,%2,%3};"
        : "+f"(c[0]), "+f"(c[1]), "+f"(c[2]), "+f"(c[3])
        : "r"(a[0]), "r"(a[1]), "r"(a[2]), "r"(a[3]), "r"(b0), "r"(b1));
}
#define LDX4(r, addr) \
    asm volatile("ldmatrix.sync.aligned.m8n8.x4.shared.b16 {%0,%1,%2,%3}, [%4];" \
                 : "=r"((r)[0]), "=r"((r)[1]), "=r"((r)[2]), "=r"((r)[3])        \
                 : "r"(addr))

// ---------------- x -> fp16 chunk converter ----------------------------------
#define NCH_TOTAL ((N0 * FH) / 8)
__device__ __forceinline__ void conv_chunk(const float4* __restrict__ x4,
                                           uint4* __restrict__ Xh4, int i) {
    float4 v0 = x4[2 * i], v1 = x4[2 * i + 1];
    Xh4[i] = make_uint4(
        pack2(__float2half_rn(v0.x), __float2half_rn(v0.y)),
        pack2(__float2half_rn(v0.z), __float2half_rn(v0.w)),
        pack2(__float2half_rn(v1.x), __float2half_rn(v1.y)),
        pack2(__float2half_rn(v1.z), __float2half_rn(v1.w)));
}

// ---------------- folded prep bodies ------------------------------------------
__device__ __forceinline__ void transpose_body(
    const float* __restrict__ W, __half* __restrict__ Bh,
    int bx, int by, int tx, int ty, float (*t)[33]) {
    int n0 = bx * 32, k0 = by * 32;
    for (int yy = ty; yy < 32; yy += 8)
        t[yy][tx] = W[(size_t)(k0 + yy) * FH + n0 + tx];
    __syncthreads();
    for (int yy = ty; yy < 32; yy += 8)
        Bh[(size_t)(n0 + yy) * FH + k0 + tx] = __float2half_rn(t[tx][yy]);
}

__device__ __forceinline__ void wcomb_body(
    int k, int lane,
    const float* __restrict__ Wlin, const float* __restrict__ Whead,
    const float* __restrict__ blin, const float* __restrict__ bhead,
    float* __restrict__ Wcomb, float* __restrict__ bcomb) {
    const float* rowv = (k < FH) ? (Wlin + (size_t)k * FH) : blin;
    float acc[C_OUT];
#pragma unroll
    for (int c = 0; c < C_OUT; ++c) acc[c] = 0.f;
    for (int j = lane; j < FH; j += 32) {
        float v = rowv[j];
        const float* w = Whead + (size_t)j * C_OUT;
#pragma unroll
        for (int c = 0; c < C_OUT; ++c) acc[c] += v * w[c];
    }
#pragma unroll
    for (int off = 16; off > 0; off >>= 1)
#pragma unroll
        for (int c = 0; c < C_OUT; ++c)
            acc[c] += __shfl_down_sync(0xFFFFFFFFu, acc[c], off);
    if (lane == 0) {
        if (k < FH) {
#pragma unroll
            for (int c = 0; c < C_OUT; ++c) Wcomb[(size_t)k * C_OUT + c] = acc[c];
        } else {
#pragma unroll
            for (int c = 0; c < C_OUT; ++c) bcomb[c] = acc[c] + bhead[c];
        }
    }
}

__device__ __forceinline__ void wfold_body(
    int idx, int lane,
    const float* __restrict__ Wrel2, const float* __restrict__ Wroot2,
    const float* __restrict__ brel2,
    const float* __restrict__ Wcomb, const float* __restrict__ bcomb,
    float* __restrict__ Wc2, float* __restrict__ bc2) {
    float acc[C_OUT];
#pragma unroll
    for (int c = 0; c < C_OUT; ++c) acc[c] = 0.f;
    if (idx < 2 * FH) {
        int m = idx >> 9, k = idx & (FH - 1);
        const float* W = m ? Wroot2 : Wrel2;
        for (int j = lane; j < FH; j += 32) {
            float v = W[(size_t)k * FH + j];
            const float* wc = Wcomb + (size_t)j * C_OUT;
#pragma unroll
            for (int c = 0; c < C_OUT; ++c) acc[c] += v * wc[c];
        }
#pragma unroll
        for (int off = 16; off > 0; off >>= 1)
#pragma unroll
            for (int c = 0; c < C_OUT; ++c)
                acc[c] += __shfl_down_sync(0xFFFFFFFFu, acc[c], off);
        if (lane == 0) {
            int p = k >> 1, dd = k & 1;
            float* dst = Wc2 + (size_t)m * WC2_MAT + p * WC2_PITCH + dd * C_OUT;
#pragma unroll
            for (int c = 0; c < C_OUT; ++c) dst[c] = acc[c];
        }
    } else if (idx == 2 * FH) {
        for (int j = lane; j < FH; j += 32) {
            float v = brel2[j];
            const float* wc = Wcomb + (size_t)j * C_OUT;
#pragma unroll
            for (int c = 0; c < C_OUT; ++c) acc[c] += v * wc[c];
        }
#pragma unroll
        for (int off = 16; off > 0; off >>= 1)
#pragma unroll
            for (int c = 0; c < C_OUT; ++c)
                acc[c] += __shfl_down_sync(0xFFFFFFFFu, acc[c], off);
        if (lane == 0) {
#pragma unroll
            for (int c = 0; c < C_OUT; ++c) bc2[c] = acc[c] + bcomb[c];
        }
    }
}

// ---------------- launch A: hist + ALL conv + transposes + wcomb --------------
__global__ void hist_all(const int* __restrict__ d1, const int* __restrict__ d2,
                         int* __restrict__ c1, int* __restrict__ c2,
                         int hb, int cb, int tb,
                         const float4* __restrict__ x4, uint4* __restrict__ Xh4,
                         const float* __restrict__ W0, const float* __restrict__ W1,
                         __half* __restrict__ Wt,
                         const float* __restrict__ Wlin, const float* __restrict__ Whead,
                         const float* __restrict__ blin, const float* __restrict__ bhead,
                         float* __restrict__ Wcomb, float* __restrict__ bcomb) {
    int bid = blockIdx.x;
    if (bid < hb) {
        int e = bid * blockDim.x + threadIdx.x;
        if (e < E1) atomicAdd(&c1[d1[e]], 1);
        else if (e < E1 + E2) atomicAdd(&c2[d2[e - E1]], 1);
    } else if (bid < hb + cb) {
        int i = (bid - hb) * blockDim.x + threadIdx.x;
        if (i < NCH_TOTAL) conv_chunk(x4, Xh4, i);
    } else if (bid < hb + cb + tb) {
        __shared__ float t[32][33];
        int idx = bid - hb - cb;
        int z = idx >> 8;
        int rem = idx & 255;
        const float* W = z ? W1 : W0;
        __half* Bh = Wt + (size_t)(2 * z) * FH * FH;
        transpose_body(W, Bh, rem & 15, rem >> 4,
                       threadIdx.x & 31, threadIdx.x >> 5, t);
    } else {
        int k = (bid - hb - cb - tb) * 8 + (threadIdx.x >> 5);
        if (k <= FH)
            wcomb_body(k, threadIdx.x & 31, Wlin, Whead, blin, bhead, Wcomb, bcomb);
    }
}

// ---------------- launch B: scan ----------------------------------------------
__global__ __launch_bounds__(1024) void scan_both(
    const int* __restrict__ c1, int* __restrict__ r1, int* __restrict__ p1,
    const int* __restrict__ c2, int* __restrict__ r2, int* __restrict__ p2) {
    const int n = blockIdx.x ? N2 : N1;
    const int* cnt = blockIdx.x ? c2 : c1;
    int* rowptr = blockIdx.x ? r2 : r1;
    int* pos    = blockIdx.x ? p2 : p1;
    __shared__ int ts[1024];
    const int t = threadIdx.x;
    const int C = (n + 1023) >> 10;
    int local[20];
    int s = 0;
    for (int j = 0; j < C; ++j) {
        int idx = t * C + j;
        int v = (idx < n) ? cnt[idx] : 0;
        local[j] = s; s += v;
    }
    ts[t] = s;
    __syncthreads();
    for (int off = 1; off < 1024; off <<= 1) {
        int v = (t >= off) ? ts[t - off] : 0;
        __syncthreads();
        ts[t] += v;
        __syncthreads();
    }
    int base = (t > 0) ? ts[t - 1] : 0;
    for (int j = 0; j < C; ++j) {
        int idx = t * C + j;
        if (idx < n) { int r = base + local[j]; rowptr[idx] = r; pos[idx] = r; }
    }
    if (t == 1023) rowptr[n] = ts[1023];
}

// ---------------- launch C: fill + wfold + cnt re-zero -------------------------
__global__ void fill_wf_zero(const int* __restrict__ d1, const int* __restrict__ s1,
                             int* __restrict__ p1, int* __restrict__ e1,
                             const int* __restrict__ d2, const int* __restrict__ s2,
                             int* __restrict__ p2, int* __restrict__ e2,
                             int fb, int wb,
                             const float* __restrict__ Wrel2, const float* __restrict__ Wroot2,
                             const float* __restrict__ brel2,
                             const float* __restrict__ Wcomb, const float* __restrict__ bcomb,
                             float* __restrict__ Wc2, float* __restrict__ bc2,
                             int* __restrict__ c1, int* __restrict__ c2) {
    int bid = blockIdx.x;
    if (bid < fb) {
        int e = bid * blockDim.x + threadIdx.x;
        if (e < E1) {
            int p = atomicAdd(&p1[d1[e]], 1);
            e1[p] = s1[e];
        } else if (e < E1 + E2) {
            int q = e - E1;
            int p = atomicAdd(&p2[d2[q]], 1);
            e2[p] = s2[q];
        }
    } else if (bid < fb + wb) {
        int idx = (bid - fb) * 8 + (threadIdx.x >> 5);
        wfold_body(idx, threadIdx.x & 31, Wrel2, Wroot2, brel2, Wcomb, bcomb,
                   Wc2, bc2);
    } else {
        int i = (bid - fb - wb) * blockDim.x + threadIdx.x;
        if (i < N1) c1[i] = 0;
        else if (i < N1 + N2) c2[i - N1] = 0;
    }
}

// ---------------- gather: persistent 888 blocks, static range + local cursor --
// fp32 adds (R14 codegen: high-reg MLP). Subrow u = row*2 + half.
#define GBLOCKS 888
__global__ void gather_hi(const __half* __restrict__ Xh,
                          const int* __restrict__ esrc,
                          const int* __restrict__ rowptr, int nrows,
                          __half* __restrict__ Ah) {
    __shared__ int cur;
    const int nsub = nrows * 2;
    const int lo = (int)(((long long)blockIdx.x * nsub) / GBLOCKS);
    const int hi = (int)(((long long)(blockIdx.x + 1) * nsub) / GBLOCKS);
    if (threadIdx.x == 0) cur = lo;
    __syncthreads();
    const int lane = threadIdx.x & 31;
    for (;;) {
        int sub = 0;
        if (lane == 0) sub = atomicAdd(&cur, 1);
        sub = __shfl_sync(0xFFFFFFFFu, sub, 0);
        if (sub >= hi) break;
        const int row = sub >> 1;
        const int colb = (sub & 1) * 256 + lane * 8;
        const int beg = rowptr[row], end = rowptr[row + 1];
        float acc[8];
#pragma unroll
        for (int j = 0; j < 8; ++j) acc[j] = 0.f;
        int i = beg;
        for (; i + 4 <= end; i += 4) {
            uint4 U0 = *(const uint4*)(Xh + (size_t)__ldg(&esrc[i])     * FH + colb);
            uint4 U1 = *(const uint4*)(Xh + (size_t)__ldg(&esrc[i + 1]) * FH + colb);
            uint4 U2 = *(const uint4*)(Xh + (size_t)__ldg(&esrc[i + 2]) * FH + colb);
            uint4 U3 = *(const uint4*)(Xh + (size_t)__ldg(&esrc[i + 3]) * FH + colb);
            uint32_t w0[4] = {U0.x, U0.y, U0.z, U0.w};
            uint32_t w1[4] = {U1.x, U1.y, U1.z, U1.w};
            uint32_t w2[4] = {U2.x, U2.y, U2.z, U2.w};
            uint32_t w3[4] = {U3.x, U3.y, U3.z, U3.w};
#pragma unroll
            for (int j = 0; j < 4; ++j) {
                float2 a = h2f(w0[j]), b = h2f(w1[j]);
                float2 c = h2f(w2[j]), d = h2f(w3[j]);
                acc[2 * j]     += (a.x + b.x) + (c.x + d.x);
                acc[2 * j + 1] += (a.y + b.y) + (c.y + d.y);
            }
        }
        for (; i < end; ++i) {
            uint4 U0 = *(const uint4*)(Xh + (size_t)__ldg(&esrc[i]) * FH + colb);
            uint32_t w0[4] = {U0.x, U0.y, U0.z, U0.w};
#pragma unroll
            for (int j = 0; j < 4; ++j) {
                float2 a = h2f(w0[j]);
                acc[2 * j]     += a.x;
                acc[2 * j + 1] += a.y;
            }
        }
        uint4 o4;
        o4.x = pack2(__float2half_rn(acc[0]), __float2half_rn(acc[1]));
        o4.y = pack2(__float2half_rn(acc[2]), __float2half_rn(acc[3]));
        o4.z = pack2(__float2half_rn(acc[4]), __float2half_rn(acc[5]));
        o4.w = pack2(__float2half_rn(acc[6]), __float2half_rn(acc[7]));
        *(uint4*)(Ah + (size_t)row * FH + colb) = o4;
    }
}

// ---------------- layer-1 GEMM (hi-only, 3-stage pipeline) -------------------
#define SA 40
#define NBUF 3

__global__ __launch_bounds__(256) void gemm1_hi(
    const __half* __restrict__ A0, const __half* __restrict__ B0,
    const __half* __restrict__ A1, const __half* __restrict__ B1,
    const float* __restrict__ bias,
    __half* __restrict__ Ch, int M) {
    extern __shared__ __half sm[];
    const int tid = threadIdx.x;
    const int lane = tid & 31;
    const int wid = tid >> 5;
    const int wm = wid & 3;
    const int wn = wid >> 2;
    const int m0 = blockIdx.y * 128;
    const int n0 = blockIdx.x * 128;

    float acc[2][8][4];
#pragma unroll
    for (int i = 0; i < 2; ++i)
#pragma unroll
        for (int j = 0; j < 8; ++j)
#pragma unroll
            for (int q = 0; q < 4; ++q) acc[i][j][q] = 0.f;

    const int r0 = tid >> 2;
    const int c8 = (tid & 3) * 8;

    auto tile_off = [&](int buf, int t, int row, int col) -> uint32_t {
        return (uint32_t)((((buf * 2 + t) * 128 + row) * SA + col) * 2);
    };
    const uint32_t smb = smem_u32(sm);

    constexpr int NST = 32;
    auto issue = [&](int buf, int s) {
        const int src = s >> 4;
        const int k0 = (s & 15) * 32;
        const __half* A = src ? A1 : A0;
        const __half* B = src ? B1 : B0;
#pragma unroll
        for (int i = 0; i < 2; ++i) {
            int row = r0 + i * 64;
            int gm = m0 + row;
            cp_async16(smb + tile_off(buf, 0, row, c8),
                       A + (size_t)gm * FH + k0 + c8, gm < M ? 16 : 0);
            cp_async16(smb + tile_off(buf, 1, row, c8),
                       B + (size_t)(n0 + row) * FH + k0 + c8, 16);
        }
        cp_commit();
    };

    issue(0, 0);
    issue(1, 1);

    const int lrow = lane & 15;
    const int lcol = (lane >> 4) << 3;
    const int fr = lane >> 2;
    const int fc = (lane & 3) * 2;

#pragma unroll 1
    for (int s = 0; s < NST; ++s) {
        cp_wait1();
        __syncthreads();
        if (s + 2 < NST) issue((s + 2) % NBUF, s + 2);
        else cp_commit();
        const int buf = s % NBUF;
#pragma unroll
        for (int kk = 0; kk < 32; kk += 16) {
            uint32_t ah[2][4], bb[4][4];
#pragma unroll
            for (int mi = 0; mi < 2; ++mi) {
                int rb = wm * 32 + mi * 16 + lrow;
                LDX4(ah[mi], smb + tile_off(buf, 0, rb, kk + lcol));
            }
#pragma unroll
            for (int np = 0; np < 4; ++np) {
                int nb = wn * 64 + np * 16 + lrow;
                LDX4(bb[np], smb + tile_off(buf, 1, nb, kk + lcol));
            }
#pragma unroll
            for (int np = 0; np < 4; ++np) {
#pragma unroll
                for (int mi = 0; mi < 2; ++mi) {
                    mma16816(acc[mi][2 * np],     ah[mi], bb[np][0], bb[np][2]);
                    mma16816(acc[mi][2 * np + 1], ah[mi], bb[np][1], bb[np][3]);
                }
            }
        }
    }

    // epilogue: relu + fp16
#pragma unroll
    for (int mi = 0; mi < 2; ++mi) {
#pragma unroll
        for (int half = 0; half < 2; ++half) {
            int row = m0 + wm * 32 + mi * 16 + fr + half * 8;
            if (row >= M) continue;
#pragma unroll
            for (int ni = 0; ni < 8; ++ni) {
                int col = n0 + wn * 64 + ni * 8 + fc;
                float v0 = fmaxf(acc[mi][ni][half * 2 + 0] + bias[col], 0.f);
                float v1 = fmaxf(acc[mi][ni][half * 2 + 1] + bias[col + 1], 0.f);
                *(uint32_t*)(Ch + (size_t)row * FH + col) =
                    pack2(__float2half_rn(v0), __float2half_rn(v1));
            }
        }
    }
}

// ---------------- fused layer 2 + head ---------------------------------------
__global__ __launch_bounds__(256) void layer2_fused(
    const uint32_t* __restrict__ Hh32,
    const int* __restrict__ esrc, const int* __restrict__ rowptr,
    const float* __restrict__ Wc2, const float* __restrict__ bc2,
    float* __restrict__ out) {
    __shared__ float ws[2 * WC2_MAT];
    __shared__ float bs[C_OUT];
    for (int i = threadIdx.x; i < 2 * WC2_MAT; i += 256) ws[i] = Wc2[i];
    if (threadIdx.x < C_OUT) bs[threadIdx.x] = bc2[threadIdx.x];
    __syncthreads();

    const int lane = threadIdx.x & 31;
    int row = blockIdx.x * 8 + (threadIdx.x >> 5);
    if (row >= N2) return;
    const int beg = rowptr[row], end = rowptr[row + 1];

    float agg[16];
#pragma unroll
    for (int j = 0; j < 16; ++j) agg[j] = 0.f;
    for (int i = beg; i < end; ++i) {
        const uint32_t* hrow = Hh32 + (size_t)__ldg(&esrc[i]) * 256;
#pragma unroll
        for (int q = 0; q < 8; ++q) {
            float2 f = h2f(hrow[lane + 32 * q]);
            agg[2 * q]     += f.x;
            agg[2 * q + 1] += f.y;
        }
    }
    float hr[16];
    {
        const uint32_t* rrow = Hh32 + (size_t)row * 256;
#pragma unroll
        for (int q = 0; q < 8; ++q) {
            float2 f = h2f(rrow[lane + 32 * q]);
            hr[2 * q]     = f.x;
            hr[2 * q + 1] = f.y;
        }
    }
    float res[C_OUT];
#pragma unroll
    for (int c = 0; c < C_OUT; ++c) res[c] = 0.f;
    const float* wrel  = ws;
    const float* wroot = ws + WC2_MAT;
#pragma unroll
    for (int q = 0; q < 8; ++q) {
        int p = lane + 32 * q;
        const float* w0 = wrel  + p * WC2_PITCH;
        const float* w1 = wroot + p * WC2_PITCH;
#pragma unroll
        for (int c = 0; c < C_OUT; ++c) {
            res[c] += agg[2 * q]     * w0[c]
                    + agg[2 * q + 1] * w0[C_OUT + c]
                    + hr[2 * q]      * w1[c]
                    + hr[2 * q + 1]  * w1[C_OUT + c];
        }
    }
#pragma unroll
    for (int off = 16; off > 0; off >>= 1)
#pragma unroll
        for (int c = 0; c < C_OUT; ++c)
            res[c] += __shfl_down_sync(0xFFFFFFFFu, res[c], off);
    if (lane == 0) {
#pragma unroll
        for (int c = 0; c < C_OUT; ++c)
            out[(size_t)row * C_OUT + c] = res[c] + bs[c];
    }
}

// ---------------------------------------------------------------------------
extern "C" void kernel_launch(void* const* d_in, const int* in_sizes, int n_in,
                              void* d_out, int out_size) {
    const float* x     = (const float*)d_in[0];
    const int*   src1  = (const int*)  d_in[1];
    const int*   dst1  = (const int*)  d_in[2];
    const int*   src2  = (const int*)  d_in[3];
    const int*   dst2  = (const int*)  d_in[4];
    const float* Wrel1 = (const float*)d_in[5];
    const float* brel1 = (const float*)d_in[6];
    const float* Wroot1= (const float*)d_in[7];
    const float* Wrel2 = (const float*)d_in[8];
    const float* brel2 = (const float*)d_in[9];
    const float* Wroot2= (const float*)d_in[10];
    const float* Wlin  = (const float*)d_in[11];
    const float* blin  = (const float*)d_in[12];
    const float* Whead = (const float*)d_in[13];
    const float* bhead = (const float*)d_in[14];
    float* out = (float*)d_out;

    float *Wcomb, *bcomb, *Wc2, *bc2;
    __half *Xh, *A1h, *Hh, *Wt;
    int *cnt1, *rp1, *pos1, *esrc1, *cnt2, *rp2, *pos2, *esrc2;
    cudaGetSymbolAddress((void**)&Xh,   g_Xh);
    cudaGetSymbolAddress((void**)&A1h,  g_A1h);
    cudaGetSymbolAddress((void**)&Hh,   g_Hh);
    cudaGetSymbolAddress((void**)&Wt,   g_Wt);
    cudaGetSymbolAddress((void**)&Wcomb, g_Wcomb);
    cudaGetSymbolAddress((void**)&bcomb, g_bcomb);
    cudaGetSymbolAddress((void**)&Wc2,  g_Wc2);
    cudaGetSymbolAddress((void**)&bc2,  g_bc2);
    cudaGetSymbolAddress((void**)&cnt1, g_cnt1);
    cudaGetSymbolAddress((void**)&rp1,  g_rp1);
    cudaGetSymbolAddress((void**)&pos1, g_pos1);
    cudaGetSymbolAddress((void**)&esrc1, g_esrc1);
    cudaGetSymbolAddress((void**)&cnt2, g_cnt2);
    cudaGetSymbolAddress((void**)&rp2,  g_rp2);
    cudaGetSymbolAddress((void**)&pos2, g_pos2);
    cudaGetSymbolAddress((void**)&esrc2, g_esrc2);
    __half* Wrel1T = Wt;
    __half* Wroot1T = Wt + (size_t)2 * FH * FH;

    constexpr int GSMEM = NBUF * 2 * 128 * SA * 2;  // 61440 B
    cudaFuncSetAttribute(gemm1_hi,
                         cudaFuncAttributeMaxDynamicSharedMemorySize, GSMEM);

    // ---- launch A: hist + ALL conv + transposes + wcomb ----
    {
        int hb = (E1 + E2 + 255) / 256;          // 2344
        int cb = (NCH_TOTAL + 255) / 256;        // 25000
        int tb = 512;
        int wb = (FH + 1 + 7) / 8;               // 65
        hist_all<<<hb + cb + tb + wb, 256>>>(
            dst1, dst2, cnt1, cnt2, hb, cb, tb,
            (const float4*)x, (uint4*)Xh,
            Wrel1, Wroot1, Wt,
            Wlin, Whead, blin, bhead, Wcomb, bcomb);
    }
    // ---- launch B: scan ----
    scan_both<<<2, 1024>>>(cnt1, rp1, pos1, cnt2, rp2, pos2);
    // ---- launch C: fill + wfold + cnt re-zero ----
    {
        int fb = (E1 + E2 + 255) / 256;          // 2344
        int wb = (2 * FH + 1 + 7) / 8;           // 129
        int zb = (N1 + N2 + 255) / 256;          // 94
        fill_wf_zero<<<fb + wb + zb, 256>>>(
            dst1, src1, pos1, esrc1, dst2, src2, pos2, esrc2, fb, wb,
            Wrel2, Wroot2, brel2, Wcomb, bcomb, Wc2, bc2, cnt1, cnt2);
    }

    // ---- layer 1 ----
    gather_hi<<<GBLOCKS, 256>>>(Xh, esrc1, rp1, N1, A1h);
    {
        dim3 grid(FH / 128, (N1 + 127) / 128);
        gemm1_hi<<<grid, 256, GSMEM>>>(
            A1h, Wrel1T, Xh, Wroot1T, brel1, Hh, N1);
    }

    // ---- fused layer 2 + head ----
    layer2_fused<<<(N2 + 7) / 8, 256>>>(
        (const uint32_t*)Hh, esrc2, rp2, Wc2, bc2, out);

    (void)in_sizes; (void)n_in; (void)out_size;
}